// round 1
// baseline (speedup 1.0000x reference)
#include <cuda_runtime.h>
#include <cstdint>

// Problem constants
#define HWDIM 9216            // H*W = 96*96
#define NB 16                 // batch
#define NPOS (HWDIM * NB)     // 147456 spatial positions
#define CIN 256
#define HCH 10                // h
#define NPARTS 6
#define KROWS 70              // 10 (w_dp_f) + 60 (w_proj flattened)
#define PART_SZ ((size_t)NPARTS * NB * HCH * HWDIM)  // 8,847,360

typedef unsigned long long u64;

// Scratch: Y[k][n]  (k = 0..9 fdp rows, 10..69 proj rows), 41.3 MB
__device__ float g_Y[(size_t)KROWS * NPOS];

__device__ __forceinline__ u64 fma2(u64 a, u64 b, u64 c) {
    u64 d;
    asm("fma.rn.f32x2 %0, %1, %2, %3;" : "=l"(d) : "l"(a), "l"(b), "l"(c));
    return d;
}

__device__ __forceinline__ u64 dup2(float v) {
    u64 p;
    asm("mov.b64 %0, {%1, %2};" : "=l"(p) : "f"(v), "f"(v));
    return p;
}

__device__ __forceinline__ float sigm(float x) {
    return 1.0f / (1.0f + expf(-x));
}

// ---------------------------------------------------------------------------
// Kernel A: Y[70, NPOS] = [w_dp_f(10x256); w_proj(60x256)] @ p_fea
// f32x2: each thread handles 2 adjacent positions, 35 of the 70 output rows.
// blockDim = 512 (two k-halves of 256 threads), 512 positions per block.
// smem: duplicated-weight f32x2 table, 70*256*8 = 143360 B.
// ---------------------------------------------------------------------------
extern __shared__ u64 s_wdup[];

__global__ void __launch_bounds__(512, 1)
gemm_kernel(const float* __restrict__ p_fea,
            const float* __restrict__ w_dp_f,
            const float* __restrict__ w_proj) {
    // Build duplicated-weight table
    for (int i = threadIdx.x; i < KROWS * CIN; i += 512) {
        float v = (i < HCH * CIN) ? w_dp_f[i] : w_proj[i - HCH * CIN];
        s_wdup[i] = dup2(v);
    }
    __syncthreads();

    const int tid   = threadIdx.x;
    const int halfk = tid >> 8;        // 0 or 1 -> rows [0,35) or [35,70)
    const int tpos  = tid & 255;
    const int n0    = blockIdx.x * 512 + tpos * 2;   // even, never crosses batch

    const int b = n0 / HWDIM;
    const int s = n0 - b * HWDIM;
    const float* xptr = p_fea + (size_t)b * CIN * HWDIM + s;

    u64 acc[35];
#pragma unroll
    for (int k = 0; k < 35; ++k) acc[k] = 0ull;   // bits of {0.f,0.f}

    const u64* wrow = s_wdup + halfk * 35 * CIN;

    u64 xv = *(const u64*)(xptr);
#pragma unroll 1
    for (int c = 0; c < CIN; ++c) {
        u64 xn = 0ull;
        if (c + 1 < CIN) xn = *(const u64*)(xptr + (size_t)(c + 1) * HWDIM);
#pragma unroll
        for (int k = 0; k < 35; ++k)
            acc[k] = fma2(xv, wrow[k * CIN + c], acc[k]);
        xv = xn;
    }

    const int krow0 = halfk * 35;
#pragma unroll
    for (int k = 0; k < 35; ++k)
        *(u64*)(g_Y + (size_t)(krow0 + k) * NPOS + n0) = acc[k];
}

// ---------------------------------------------------------------------------
// Kernel B: per-position graph epilogue. 1 thread = 1 position.
// ---------------------------------------------------------------------------
__global__ void __launch_bounds__(256)
epi_kernel(const float* __restrict__ xp_stack,
           const float* __restrict__ xh_stack,
           const float* __restrict__ w_att,  const float* __restrict__ b_att,
           const float* __restrict__ w_dp_x, const float* __restrict__ b_dp,
           const float* __restrict__ b_proj,
           const float* __restrict__ w_gate, const float* __restrict__ b_gate,
           const float* __restrict__ w_upd,  const float* __restrict__ b_upd,
           float* __restrict__ out) {
    __shared__ float cw[2222];
    for (int i = threadIdx.x; i < 2222; i += 256) {
        float v;
        if      (i < 60)   v = w_att[i];
        else if (i < 66)   v = b_att[i - 60];
        else if (i < 166)  v = w_dp_x[i - 66];
        else if (i < 176)  v = b_dp[i - 166];
        else if (i < 236)  v = b_proj[i - 176];
        else if (i < 356)  v = w_gate[i - 236];
        else if (i < 362)  v = b_gate[i - 356];
        else if (i < 2162) v = w_upd[i - 362];
        else               v = b_upd[i - 2162];
        cw[i] = v;
    }
    __syncthreads();

    const float* sW_att  = cw;
    const float* sB_att  = cw + 60;
    const float* sW_dpx  = cw + 66;
    const float* sB_dp   = cw + 166;
    const float* sB_proj = cw + 176;
    const float* sW_gate = cw + 236;
    const float* sB_gate = cw + 356;
    const float* sW_upd  = cw + 362;
    const float* sB_upd  = cw + 2162;

    const int n = blockIdx.x * 256 + threadIdx.x;
    if (n >= NPOS) return;
    const int b = n / HWDIM;
    const int s = n - b * HWDIM;

    // fdp = Y rows 0..9 + b_dp
    float fdp[HCH];
#pragma unroll
    for (int d = 0; d < HCH; ++d)
        fdp[d] = g_Y[(size_t)d * NPOS + n] + sB_dp[d];

    float att[NPARTS];
    float dp1[HCH], S[HCH], xp1[HCH];
    float attsum = 0.f;
#pragma unroll
    for (int d = 0; d < HCH; ++d) S[d] = 0.f;

    // Pass 1: att[p], dp[p]; keep dp[1], xp[1]; accumulate S = sum_{p!=1} att_p*dp_p
#pragma unroll
    for (int p = 0; p < NPARTS; ++p) {
        float xq[HCH];
#pragma unroll
        for (int d = 0; d < HCH; ++d)
            xq[d] = xp_stack[((size_t)(p * (NB * HCH) + b * HCH + d)) * HWDIM + s];

        float a = sB_att[p];
#pragma unroll
        for (int d = 0; d < HCH; ++d) a += sW_att[p * HCH + d] * xq[d];
        a = sigm(a);
        att[p] = a;

        float dpv[HCH];
#pragma unroll
        for (int d = 0; d < HCH; ++d) {
            float u = fdp[d];
#pragma unroll
            for (int e = 0; e < HCH; ++e) u += sW_dpx[d * HCH + e] * xq[e];
            dpv[d] = fmaxf(u, 0.f);
        }
        if (p == 1) {
#pragma unroll
            for (int d = 0; d < HCH; ++d) { dp1[d] = dpv[d]; xp1[d] = xq[d]; }
        } else {
            attsum += a;
#pragma unroll
            for (int d = 0; d < HCH; ++d) S[d] += a * dpv[d];
        }
    }

    // Pass 2: xpp, xhp, update, stores
#pragma unroll
    for (int p = 0; p < NPARTS; ++p) {
        float xq[HCH];
        if (p == 1) {
#pragma unroll
            for (int d = 0; d < HCH; ++d) xq[d] = xp1[d];
        } else {
#pragma unroll
            for (int d = 0; d < HCH; ++d)
                xq[d] = xp_stack[((size_t)(p * (NB * HCH) + b * HCH + d)) * HWDIM + s];
        }

        float xppv[HCH];
        if (p == 1) {
#pragma unroll
            for (int d = 0; d < HCH; ++d)
                xppv[d] = att[1] * (S[d] + attsum * xp1[d]);
        } else {
            const float aa = att[1] * att[p];
#pragma unroll
            for (int d = 0; d < HCH; ++d)
                xppv[d] = aa * (dp1[d] + xq[d]);
        }

        const int hf = (p < 4) ? 0 : 1;
        float g = sB_gate[p];
#pragma unroll
        for (int d = 0; d < HCH; ++d) {
            float xh = xh_stack[((size_t)(hf * (NB * HCH) + b * HCH + d)) * HWDIM + s];
            g += sW_gate[p * 2 * HCH + d] * xh;
        }
#pragma unroll
        for (int d = 0; d < HCH; ++d)
            g += sW_gate[p * 2 * HCH + HCH + d] * xq[d];
        g = sigm(g);

        float xhpv[HCH];
#pragma unroll
        for (int d = 0; d < HCH; ++d)
            xhpv[d] = g * (g_Y[(size_t)(HCH + p * HCH + d) * NPOS + n] + sB_proj[p * HCH + d]);

        // att_Update + stores
#pragma unroll
        for (int d = 0; d < HCH; ++d) {
            float u = sB_upd[p * HCH + d];
            const float* wr = sW_upd + (p * HCH + d) * (3 * HCH);
#pragma unroll
            for (int e = 0; e < HCH; ++e) u += wr[e] * xq[e];
#pragma unroll
            for (int e = 0; e < HCH; ++e) u += wr[HCH + e] * xppv[e];
#pragma unroll
            for (int e = 0; e < HCH; ++e) u += wr[2 * HCH + e] * xhpv[e];
            const float o = xq[d] + fmaxf(u, 0.f);

            const size_t oidx = ((size_t)(p * (NB * HCH) + b * HCH + d)) * HWDIM + s;
            out[oidx]               = o;        // xp_out
            out[PART_SZ + oidx]     = xppv[d];  // xpp
            out[2 * PART_SZ + oidx] = xhpv[d];  // xhp
        }
    }
}

// ---------------------------------------------------------------------------
extern "C" void kernel_launch(void* const* d_in, const int* in_sizes, int n_in,
                              void* d_out, int out_size) {
    const float* p_fea  = (const float*)d_in[0];
    const float* xp     = (const float*)d_in[1];
    const float* xh     = (const float*)d_in[2];
    const float* w_att  = (const float*)d_in[3];
    const float* b_att  = (const float*)d_in[4];
    const float* w_dp_f = (const float*)d_in[5];
    const float* w_dp_x = (const float*)d_in[6];
    const float* b_dp   = (const float*)d_in[7];
    const float* w_proj = (const float*)d_in[8];
    const float* b_proj = (const float*)d_in[9];
    const float* w_gate = (const float*)d_in[10];
    const float* b_gate = (const float*)d_in[11];
    const float* w_upd  = (const float*)d_in[12];
    const float* b_upd  = (const float*)d_in[13];
    float* out = (float*)d_out;

    const int smem = KROWS * CIN * 8;  // 143360 B
    cudaFuncSetAttribute(gemm_kernel, cudaFuncAttributeMaxDynamicSharedMemorySize, smem);

    gemm_kernel<<<NPOS / 512, 512, smem>>>(p_fea, w_dp_f, w_proj);
    epi_kernel<<<NPOS / 256, 256>>>(xp, xh, w_att, b_att, w_dp_x, b_dp,
                                    b_proj, w_gate, b_gate, w_upd, b_upd, out);
}

// round 2
// speedup vs baseline: 1.4438x; 1.4438x over previous
#include <cuda_runtime.h>
#include <cstdint>

// Problem constants
#define HWDIM 9216            // H*W = 96*96
#define NB 16                 // batch
#define NPOS (HWDIM * NB)     // 147456 spatial positions
#define CIN 256
#define HCH 10                // h
#define NPARTS 6
#define KROWS 70              // 10 (w_dp_f) + 60 (w_proj flattened)
#define PART_SZ (NPARTS * NB * HCH * HWDIM)   // 8,847,360 (fits int)
#define PBH (NB * HCH * HWDIM)                // 1,474,560

typedef unsigned long long u64;

// Scratch: Y[k][n]  (k = 0..9 fdp rows, 10..69 proj rows), 41.3 MB
__device__ float g_Y[(size_t)KROWS * NPOS];

__device__ __forceinline__ u64 fma2(u64 a, u64 b, u64 c) {
    u64 d;
    asm("fma.rn.f32x2 %0, %1, %2, %3;" : "=l"(d) : "l"(a), "l"(b), "l"(c));
    return d;
}

__device__ __forceinline__ u64 dup2(float v) {
    u64 p;
    asm("mov.b64 %0, {%1, %2};" : "=l"(p) : "f"(v), "f"(v));
    return p;
}

__device__ __forceinline__ float sigm(float x) {
    return 1.0f / (1.0f + __expf(-x));
}

// ---------------------------------------------------------------------------
// Kernel A: Y[70, NPOS] = [w_dp_f(10x256); w_proj(60x256)] @ p_fea
//
// Grid: 144 position-tiles x 5 k-groups (g = bid % 5 so the 5 blocks sharing a
// p_fea tile are adjacent bids -> concurrent -> L2 reuse).
// Block: 256 threads. Each thread: 14 rows x 2 f32x2 position-pairs.
// Tile covers 1024 positions (pairs at s and s+512). Never crosses batch
// (HWDIM = 9*1024).
// Per 2 c-steps/thread: 14 LDS.128 (dup-weight pairs) + 4 LDG.64 + 56 FFMA2.
// ---------------------------------------------------------------------------
__global__ void __launch_bounds__(256, 2)
gemm_kernel(const float* __restrict__ p_fea,
            const float* __restrict__ w_dp_f,
            const float* __restrict__ w_proj) {
    __shared__ u64 s_w[14 * 256];     // duplicated weights for this k-group

    const int g    = blockIdx.x % 5;          // k-group: rows [14g, 14g+14)
    const int tile = blockIdx.x / 5;          // 1024-position tile

    // Build duplicated-weight table for this group's 14 rows
    for (int i = threadIdx.x; i < 14 * 256; i += 256) {
        const int r = g * 14 + (i >> 8);      // global row
        const int c = i & 255;
        float v = (r < HCH) ? w_dp_f[r * CIN + c] : w_proj[(r - HCH) * CIN + c];
        s_w[i] = dup2(v);
    }
    __syncthreads();

    const int tbase = tile * 1024;
    const int b     = tbase / HWDIM;
    const int s0    = (tbase - b * HWDIM) + threadIdx.x * 2;

    const float* x0 = p_fea + (size_t)b * (CIN * HWDIM) + s0;  // pair 0
    const float* x1 = x0 + 512;                                 // pair 1

    u64 acc[14][2];
#pragma unroll
    for (int k = 0; k < 14; ++k) { acc[k][0] = 0ull; acc[k][1] = 0ull; }

    // double-buffered x: (a*, b*) hold x[c], x[c+1] for both pairs
    u64 a0 = *(const u64*)(x0);
    u64 a1 = *(const u64*)(x1);
    u64 e0 = *(const u64*)(x0 + HWDIM);
    u64 e1 = *(const u64*)(x1 + HWDIM);

#pragma unroll 1
    for (int c = 0; c < 256; c += 2) {
        u64 na0 = 0, na1 = 0, ne0 = 0, ne1 = 0;
        if (c + 2 < 256) {
            const float* px0 = x0 + (c + 2) * HWDIM;
            const float* px1 = x1 + (c + 2) * HWDIM;
            na0 = *(const u64*)(px0);
            na1 = *(const u64*)(px1);
            ne0 = *(const u64*)(px0 + HWDIM);
            ne1 = *(const u64*)(px1 + HWDIM);
        }
#pragma unroll
        for (int k = 0; k < 14; ++k) {
            const u64 w0 = s_w[k * 256 + c];
            const u64 w1 = s_w[k * 256 + c + 1];
            acc[k][0] = fma2(a0, w0, acc[k][0]);
            acc[k][1] = fma2(a1, w0, acc[k][1]);
            acc[k][0] = fma2(e0, w1, acc[k][0]);
            acc[k][1] = fma2(e1, w1, acc[k][1]);
        }
        a0 = na0; a1 = na1; e0 = ne0; e1 = ne1;
    }

    const int n0 = tbase + threadIdx.x * 2;
#pragma unroll
    for (int k = 0; k < 14; ++k) {
        float* yrow = g_Y + (size_t)(g * 14 + k) * NPOS;
        *(u64*)(yrow + n0)       = acc[k][0];
        *(u64*)(yrow + n0 + 512) = acc[k][1];
    }
}

// ---------------------------------------------------------------------------
// Kernel B: per-position graph epilogue. 1 thread = 1 position.
// All indexing in int32; reg cap 128 for 2 blocks/SM.
// ---------------------------------------------------------------------------
__global__ void __launch_bounds__(256, 2)
epi_kernel(const float* __restrict__ xp_stack,
           const float* __restrict__ xh_stack,
           const float* __restrict__ w_att,  const float* __restrict__ b_att,
           const float* __restrict__ w_dp_x, const float* __restrict__ b_dp,
           const float* __restrict__ b_proj,
           const float* __restrict__ w_gate, const float* __restrict__ b_gate,
           const float* __restrict__ w_upd,  const float* __restrict__ b_upd,
           float* __restrict__ out) {
    __shared__ float cw[2222];
    for (int i = threadIdx.x; i < 2222; i += 256) {
        float v;
        if      (i < 60)   v = w_att[i];
        else if (i < 66)   v = b_att[i - 60];
        else if (i < 166)  v = w_dp_x[i - 66];
        else if (i < 176)  v = b_dp[i - 166];
        else if (i < 236)  v = b_proj[i - 176];
        else if (i < 356)  v = w_gate[i - 236];
        else if (i < 362)  v = b_gate[i - 356];
        else if (i < 2162) v = w_upd[i - 362];
        else               v = b_upd[i - 2162];
        cw[i] = v;
    }
    __syncthreads();

    const float* sW_att  = cw;
    const float* sB_att  = cw + 60;
    const float* sW_dpx  = cw + 66;
    const float* sB_dp   = cw + 166;
    const float* sB_proj = cw + 176;
    const float* sW_gate = cw + 236;
    const float* sB_gate = cw + 356;
    const float* sW_upd  = cw + 362;
    const float* sB_upd  = cw + 2162;

    const int n = blockIdx.x * 256 + threadIdx.x;
    const int b = n / HWDIM;
    const int s = n - b * HWDIM;
    const int bbase = b * (HCH * HWDIM) + s;   // offset of (b, d=0, s) within a part

    // fdp = Y rows 0..9 + b_dp
    float fdp[HCH];
#pragma unroll
    for (int d = 0; d < HCH; ++d)
        fdp[d] = g_Y[d * NPOS + n] + sB_dp[d];

    float att[NPARTS];
    float dp1[HCH], S[HCH], xp1[HCH];
    float attsum = 0.f;
#pragma unroll
    for (int d = 0; d < HCH; ++d) S[d] = 0.f;

    // Pass 1: att[p], dp[p]; keep dp[1], xp[1]; S = sum_{p!=1} att_p*dp_p
#pragma unroll
    for (int p = 0; p < NPARTS; ++p) {
        const float* xpp_ptr = xp_stack + p * PBH + bbase;
        float xq[HCH];
#pragma unroll
        for (int d = 0; d < HCH; ++d) xq[d] = xpp_ptr[d * HWDIM];

        float a = sB_att[p];
#pragma unroll
        for (int d = 0; d < HCH; ++d) a += sW_att[p * HCH + d] * xq[d];
        a = sigm(a);
        att[p] = a;

        float dpv[HCH];
#pragma unroll
        for (int d = 0; d < HCH; ++d) {
            float u = fdp[d];
#pragma unroll
            for (int e = 0; e < HCH; ++e) u += sW_dpx[d * HCH + e] * xq[e];
            dpv[d] = fmaxf(u, 0.f);
        }
        if (p == 1) {
#pragma unroll
            for (int d = 0; d < HCH; ++d) { dp1[d] = dpv[d]; xp1[d] = xq[d]; }
        } else {
            attsum += a;
#pragma unroll
            for (int d = 0; d < HCH; ++d) S[d] += a * dpv[d];
        }
    }

    // Pass 2: xpp, xhp, update, stores
#pragma unroll
    for (int p = 0; p < NPARTS; ++p) {
        const float* xpp_ptr = xp_stack + p * PBH + bbase;
        float xq[HCH];
        if (p == 1) {
#pragma unroll
            for (int d = 0; d < HCH; ++d) xq[d] = xp1[d];
        } else {
#pragma unroll
            for (int d = 0; d < HCH; ++d) xq[d] = xpp_ptr[d * HWDIM];
        }

        float xppv[HCH];
        if (p == 1) {
#pragma unroll
            for (int d = 0; d < HCH; ++d)
                xppv[d] = att[1] * (S[d] + attsum * xp1[d]);
        } else {
            const float aa = att[1] * att[p];
#pragma unroll
            for (int d = 0; d < HCH; ++d)
                xppv[d] = aa * (dp1[d] + xq[d]);
        }

        const int hf = (p < 4) ? 0 : 1;
        const float* xh_ptr = xh_stack + hf * PBH + bbase;
        float gsum = sB_gate[p];
#pragma unroll
        for (int d = 0; d < HCH; ++d)
            gsum += sW_gate[p * 2 * HCH + d] * xh_ptr[d * HWDIM];
#pragma unroll
        for (int d = 0; d < HCH; ++d)
            gsum += sW_gate[p * 2 * HCH + HCH + d] * xq[d];
        const float gate = sigm(gsum);

        float xhpv[HCH];
#pragma unroll
        for (int d = 0; d < HCH; ++d)
            xhpv[d] = gate * (g_Y[(HCH + p * HCH + d) * NPOS + n] + sB_proj[p * HCH + d]);

        // att_Update + stores
        float* o0 = out + p * PBH + bbase;
#pragma unroll
        for (int d = 0; d < HCH; ++d) {
            float u = sB_upd[p * HCH + d];
            const float* wr = sW_upd + (p * HCH + d) * (3 * HCH);
#pragma unroll
            for (int e = 0; e < HCH; ++e) u += wr[e] * xq[e];
#pragma unroll
            for (int e = 0; e < HCH; ++e) u += wr[HCH + e] * xppv[e];
#pragma unroll
            for (int e = 0; e < HCH; ++e) u += wr[2 * HCH + e] * xhpv[e];
            const float o = xq[d] + fmaxf(u, 0.f);

            const int doff = d * HWDIM;
            o0[doff]                = o;        // xp_out
            o0[PART_SZ + doff]      = xppv[d];  // xpp
            o0[2 * PART_SZ + doff]  = xhpv[d];  // xhp
        }
    }
}

// ---------------------------------------------------------------------------
extern "C" void kernel_launch(void* const* d_in, const int* in_sizes, int n_in,
                              void* d_out, int out_size) {
    const float* p_fea  = (const float*)d_in[0];
    const float* xp     = (const float*)d_in[1];
    const float* xh     = (const float*)d_in[2];
    const float* w_att  = (const float*)d_in[3];
    const float* b_att  = (const float*)d_in[4];
    const float* w_dp_f = (const float*)d_in[5];
    const float* w_dp_x = (const float*)d_in[6];
    const float* b_dp   = (const float*)d_in[7];
    const float* w_proj = (const float*)d_in[8];
    const float* b_proj = (const float*)d_in[9];
    const float* w_gate = (const float*)d_in[10];
    const float* b_gate = (const float*)d_in[11];
    const float* w_upd  = (const float*)d_in[12];
    const float* b_upd  = (const float*)d_in[13];
    float* out = (float*)d_out;

    gemm_kernel<<<(NPOS / 1024) * 5, 256>>>(p_fea, w_dp_f, w_proj);
    epi_kernel<<<NPOS / 256, 256>>>(xp, xh, w_att, b_att, w_dp_x, b_dp,
                                    b_proj, w_gate, b_gate, w_upd, b_upd, out);
}

// round 4
// speedup vs baseline: 1.6265x; 1.1265x over previous
#include <cuda_runtime.h>
#include <cstdint>

// Problem constants
#define HWDIM 9216            // H*W = 96*96
#define NB 16                 // batch
#define NPOS (HWDIM * NB)     // 147456 spatial positions
#define CIN 256
#define HCH 10                // h
#define NPARTS 6
#define PART_SZ (NPARTS * NB * HCH * HWDIM)   // 8,847,360 (fits int)
#define PBH (NB * HCH * HWDIM)                // 1,474,560

// Scratch: Y[k][n]  (k = 0..9 fdp rows, 10..69 proj rows), 41.3 MB
__device__ float g_Y[(size_t)70 * NPOS];

__device__ __forceinline__ float sigm(float x) {
    return 1.0f / (1.0f + __expf(-x));
}

__device__ __forceinline__ uint32_t to_tf32(float x) {
    uint32_t r;
    asm("cvt.rna.tf32.f32 %0, %1;" : "=r"(r) : "f"(x));
    return r;
}

__device__ __forceinline__ void mma_tf32(float d[4],
                                         uint32_t a0, uint32_t a1,
                                         uint32_t a2, uint32_t a3,
                                         uint32_t b0, uint32_t b1) {
    asm volatile(
        "mma.sync.aligned.m16n8k8.row.col.f32.tf32.tf32.f32 "
        "{%0,%1,%2,%3}, {%4,%5,%6,%7}, {%8,%9}, {%0,%1,%2,%3};"
        : "+f"(d[0]), "+f"(d[1]), "+f"(d[2]), "+f"(d[3])
        : "r"(a0), "r"(a1), "r"(a2), "r"(a3), "r"(b0), "r"(b1));
}

// ---------------------------------------------------------------------------
// Kernel A (mma.sync tf32): Y[70, NPOS] = [w_dp_f; w_proj] @ p_fea
// CTA = 64 positions (4 m-tiles of 16). N = 80 (rows 70..79 zero-padded).
// Warp layout: mt = wid&3 (m-tile), nh = wid>>2 (5 n-tiles each).
// smem: B (80 x 256 tf32, row stride 260 words) + A chunk (64 x 64, stride 68).
// K processed in 4 chunks of 64.
// Bank math: A frag word = row*68 + k -> 4q+r distinct; B frag word =
// row*260 + k -> 4q+r distinct. Conflict-free LDS.32.
// ---------------------------------------------------------------------------
#define B_STRIDE 260
#define A_STRIDE 68
#define A_OFF    (80 * B_STRIDE)                    // 20800 words
#define GEMM_SMEM ((A_OFF + 64 * A_STRIDE) * 4)     // 100,608 bytes

extern __shared__ uint32_t sm4[];

__global__ void __launch_bounds__(256, 2)
gemm_tc(const float* __restrict__ p_fea,
        const float* __restrict__ w_dp_f,
        const float* __restrict__ w_proj) {
    const int tid  = threadIdx.x;
    const int wid  = tid >> 5;
    const int lane = tid & 31;

    // ---- weights -> smem tf32 (rows 70..79 zero)
    for (int i = tid; i < 80 * 256; i += 256) {
        const int r = i >> 8;
        const int k = i & 255;
        float v = 0.f;
        if (r < HCH)      v = w_dp_f[r * CIN + k];
        else if (r < 70)  v = w_proj[(r - HCH) * CIN + k];
        sm4[r * B_STRIDE + k] = to_tf32(v);
    }

    const int tbase = blockIdx.x * 64;
    const int b  = tbase / HWDIM;
    const int s0 = tbase - b * HWDIM;

    const int pos = tid & 63;         // position within tile (loader role)
    const int kb  = tid >> 6;         // k lane 0..3 (loader role)
    const float* gx = p_fea + (size_t)b * (CIN * HWDIM) + s0 + pos;

    const int mt = wid & 3;           // m-tile (MMA role)
    const int nh = wid >> 2;          // n-half: n-tiles [5nh, 5nh+5)
    const int q  = lane >> 2;
    const int rr = lane & 3;

    float d[5][4];
#pragma unroll
    for (int nt = 0; nt < 5; ++nt)
#pragma unroll
        for (int j = 0; j < 4; ++j) d[nt][j] = 0.f;

    uint32_t* As = sm4 + A_OFF;
    const int arow = mt * 16 + q;

#pragma unroll 1
    for (int c = 0; c < 4; ++c) {
        __syncthreads();   // protect previous chunk's A reads
        // load + convert X chunk [64 pos][64 k]
#pragma unroll
        for (int i = 0; i < 16; ++i) {
            const int k = kb + i * 4;
            As[pos * A_STRIDE + k] = to_tf32(gx[(size_t)(c * 64 + k) * HWDIM]);
        }
        __syncthreads();

        // MMA over 8 k-steps
#pragma unroll
        for (int ks = 0; ks < 8; ++ks) {
            const int k0 = ks * 8;
            const uint32_t a0 = As[arow * A_STRIDE + k0 + rr];
            const uint32_t a1 = As[(arow + 8) * A_STRIDE + k0 + rr];
            const uint32_t a2 = As[arow * A_STRIDE + k0 + 4 + rr];
            const uint32_t a3 = As[(arow + 8) * A_STRIDE + k0 + 4 + rr];
            const int kk = c * 64 + k0 + rr;
#pragma unroll
            for (int nt = 0; nt < 5; ++nt) {
                const int brow = (nh * 5 + nt) * 8 + q;
                const uint32_t b0 = sm4[brow * B_STRIDE + kk];
                const uint32_t b1 = sm4[brow * B_STRIDE + kk + 4];
                mma_tf32(d[nt], a0, a1, a2, a3, b0, b1);
            }
        }
    }

    // ---- store D to g_Y: thread t -> pos = tbase + mt*16 + q (+8), n = n0+2rr (+1)
    const int pbase = tbase + mt * 16 + q;
#pragma unroll
    for (int nt = 0; nt < 5; ++nt) {
        const int n0 = (nh * 5 + nt) * 8 + rr * 2;
        if (n0 < 70) {
            g_Y[n0 * NPOS + pbase]     = d[nt][0];
            g_Y[n0 * NPOS + pbase + 8] = d[nt][2];
        }
        if (n0 + 1 < 70) {
            g_Y[(n0 + 1) * NPOS + pbase]     = d[nt][1];
            g_Y[(n0 + 1) * NPOS + pbase + 8] = d[nt][3];
        }
    }
}

// ---------------------------------------------------------------------------
// Kernel B: per-position graph epilogue. 1 thread = 1 position.
// ---------------------------------------------------------------------------
__global__ void __launch_bounds__(256, 2)
epi_kernel(const float* __restrict__ xp_stack,
           const float* __restrict__ xh_stack,
           const float* __restrict__ w_att,  const float* __restrict__ b_att,
           const float* __restrict__ w_dp_x, const float* __restrict__ b_dp,
           const float* __restrict__ b_proj,
           const float* __restrict__ w_gate, const float* __restrict__ b_gate,
           const float* __restrict__ w_upd,  const float* __restrict__ b_upd,
           float* __restrict__ out) {
    __shared__ float cw[2222];
    for (int i = threadIdx.x; i < 2222; i += 256) {
        float v;
        if      (i < 60)   v = w_att[i];
        else if (i < 66)   v = b_att[i - 60];
        else if (i < 166)  v = w_dp_x[i - 66];
        else if (i < 176)  v = b_dp[i - 166];
        else if (i < 236)  v = b_proj[i - 176];
        else if (i < 356)  v = w_gate[i - 236];
        else if (i < 362)  v = b_gate[i - 356];
        else if (i < 2162) v = w_upd[i - 362];
        else               v = b_upd[i - 2162];
        cw[i] = v;
    }
    __syncthreads();

    const float* sW_att  = cw;
    const float* sB_att  = cw + 60;
    const float* sW_dpx  = cw + 66;
    const float* sB_dp   = cw + 166;
    const float* sB_proj = cw + 176;
    const float* sW_gate = cw + 236;
    const float* sB_gate = cw + 356;
    const float* sW_upd  = cw + 362;
    const float* sB_upd  = cw + 2162;

    const int n = blockIdx.x * 256 + threadIdx.x;
    const int b = n / HWDIM;
    const int s = n - b * HWDIM;
    const int bbase = b * (HCH * HWDIM) + s;

    float fdp[HCH];
#pragma unroll
    for (int d = 0; d < HCH; ++d)
        fdp[d] = g_Y[d * NPOS + n] + sB_dp[d];

    float att[NPARTS];
    float dp1[HCH], S[HCH], xp1[HCH];
    float attsum = 0.f;
#pragma unroll
    for (int d = 0; d < HCH; ++d) S[d] = 0.f;

#pragma unroll
    for (int p = 0; p < NPARTS; ++p) {
        const float* xpp_ptr = xp_stack + p * PBH + bbase;
        float xq[HCH];
#pragma unroll
        for (int d = 0; d < HCH; ++d) xq[d] = xpp_ptr[d * HWDIM];

        float a = sB_att[p];
#pragma unroll
        for (int d = 0; d < HCH; ++d) a += sW_att[p * HCH + d] * xq[d];
        a = sigm(a);
        att[p] = a;

        float dpv[HCH];
#pragma unroll
        for (int d = 0; d < HCH; ++d) {
            float u = fdp[d];
#pragma unroll
            for (int e = 0; e < HCH; ++e) u += sW_dpx[d * HCH + e] * xq[e];
            dpv[d] = fmaxf(u, 0.f);
        }
        if (p == 1) {
#pragma unroll
            for (int d = 0; d < HCH; ++d) { dp1[d] = dpv[d]; xp1[d] = xq[d]; }
        } else {
            attsum += a;
#pragma unroll
            for (int d = 0; d < HCH; ++d) S[d] += a * dpv[d];
        }
    }

#pragma unroll
    for (int p = 0; p < NPARTS; ++p) {
        const float* xpp_ptr = xp_stack + p * PBH + bbase;
        float xq[HCH];
        if (p == 1) {
#pragma unroll
            for (int d = 0; d < HCH; ++d) xq[d] = xp1[d];
        } else {
#pragma unroll
            for (int d = 0; d < HCH; ++d) xq[d] = xpp_ptr[d * HWDIM];
        }

        float xppv[HCH];
        if (p == 1) {
#pragma unroll
            for (int d = 0; d < HCH; ++d)
                xppv[d] = att[1] * (S[d] + attsum * xp1[d]);
        } else {
            const float aa = att[1] * att[p];
#pragma unroll
            for (int d = 0; d < HCH; ++d)
                xppv[d] = aa * (dp1[d] + xq[d]);
        }

        const int hf = (p < 4) ? 0 : 1;
        const float* xh_ptr = xh_stack + hf * PBH + bbase;
        float gsum = sB_gate[p];
#pragma unroll
        for (int d = 0; d < HCH; ++d)
            gsum += sW_gate[p * 2 * HCH + d] * xh_ptr[d * HWDIM];
#pragma unroll
        for (int d = 0; d < HCH; ++d)
            gsum += sW_gate[p * 2 * HCH + HCH + d] * xq[d];
        const float gate = sigm(gsum);

        float xhpv[HCH];
#pragma unroll
        for (int d = 0; d < HCH; ++d)
            xhpv[d] = gate * (g_Y[(HCH + p * HCH + d) * NPOS + n] + sB_proj[p * HCH + d]);

        float* o0 = out + p * PBH + bbase;
#pragma unroll
        for (int d = 0; d < HCH; ++d) {
            float u = sB_upd[p * HCH + d];
            const float* wr = sW_upd + (p * HCH + d) * (3 * HCH);
#pragma unroll
            for (int e = 0; e < HCH; ++e) u += wr[e] * xq[e];
#pragma unroll
            for (int e = 0; e < HCH; ++e) u += wr[HCH + e] * xppv[e];
#pragma unroll
            for (int e = 0; e < HCH; ++e) u += wr[2 * HCH + e] * xhpv[e];
            const float o = xq[d] + fmaxf(u, 0.f);

            const int doff = d * HWDIM;
            o0[doff]                = o;
            o0[PART_SZ + doff]      = xppv[d];
            o0[2 * PART_SZ + doff]  = xhpv[d];
        }
    }
}

// ---------------------------------------------------------------------------
extern "C" void kernel_launch(void* const* d_in, const int* in_sizes, int n_in,
                              void* d_out, int out_size) {
    const float* p_fea  = (const float*)d_in[0];
    const float* xp     = (const float*)d_in[1];
    const float* xh     = (const float*)d_in[2];
    const float* w_att  = (const float*)d_in[3];
    const float* b_att  = (const float*)d_in[4];
    const float* w_dp_f = (const float*)d_in[5];
    const float* w_dp_x = (const float*)d_in[6];
    const float* b_dp   = (const float*)d_in[7];
    const float* w_proj = (const float*)d_in[8];
    const float* b_proj = (const float*)d_in[9];
    const float* w_gate = (const float*)d_in[10];
    const float* b_gate = (const float*)d_in[11];
    const float* w_upd  = (const float*)d_in[12];
    const float* b_upd  = (const float*)d_in[13];
    float* out = (float*)d_out;

    cudaFuncSetAttribute(gemm_tc, cudaFuncAttributeMaxDynamicSharedMemorySize,
                         GEMM_SMEM);

    gemm_tc<<<NPOS / 64, 256, GEMM_SMEM>>>(p_fea, w_dp_f, w_proj);
    epi_kernel<<<NPOS / 256, 256>>>(xp, xh, w_att, b_att, w_dp_x, b_dp,
                                    b_proj, w_gate, b_gate, w_upd, b_upd, out);
}

// round 5
// speedup vs baseline: 3.2506x; 1.9985x over previous
#include <cuda_runtime.h>
#include <cstdint>

// Problem constants
#define HWDIM 9216            // H*W = 96*96
#define NB 16                 // batch
#define NPOS (HWDIM * NB)     // 147456 spatial positions
#define CIN 256
#define HCH 10                // h
#define NPARTS 6
#define PART_SZ (NPARTS * NB * HCH * HWDIM)   // 8,847,360 (fits int)
#define PBH (NB * HCH * HWDIM)                // 1,474,560

typedef unsigned long long u64;

// Scratch: Y[k][n]  (k = 0..9 fdp rows, 10..69 proj rows), 41.3 MB
__device__ float g_Y[(size_t)70 * NPOS];

// Pre-packed tf32 weights: 72 rows x 264 words (pair-packed for LDS.64 frags)
#define B_STRIDE 264
#define B_WORDS (72 * B_STRIDE)      // 19008
__device__ uint32_t g_Bw[B_WORDS];

__device__ __forceinline__ float sigm(float x) {
    return 1.0f / (1.0f + __expf(-x));
}

__device__ __forceinline__ uint32_t to_tf32(float x) {
    uint32_t r;
    asm("cvt.rna.tf32.f32 %0, %1;" : "=r"(r) : "f"(x));
    return r;
}

__device__ __forceinline__ void mma_tf32(float d[4],
                                         uint32_t a0, uint32_t a1,
                                         uint32_t a2, uint32_t a3,
                                         uint32_t b0, uint32_t b1) {
    asm volatile(
        "mma.sync.aligned.m16n8k8.row.col.f32.tf32.tf32.f32 "
        "{%0,%1,%2,%3}, {%4,%5,%6,%7}, {%8,%9}, {%0,%1,%2,%3};"
        : "+f"(d[0]), "+f"(d[1]), "+f"(d[2]), "+f"(d[3])
        : "r"(a0), "r"(a1), "r"(a2), "r"(a3), "r"(b0), "r"(b1));
}

// ---------------------------------------------------------------------------
// Prep kernel: convert weights to tf32, pair-packed layout.
// word(r, k) = r*264 + (k>>3)*8 + (k&3)*2 + ((k>>2)&1)
// so (r, K0+rr) and (r, K0+4+rr) are adjacent -> one LDS.64 per B fragment.
// Rows 70,71 and words 256..263 per row are zero.
// ---------------------------------------------------------------------------
__global__ void prep_kernel(const float* __restrict__ w_dp_f,
                            const float* __restrict__ w_proj) {
    const int r = blockIdx.x;          // 0..71
    const int k = threadIdx.x;         // 0..255
    float v = 0.f;
    if (r < HCH)      v = w_dp_f[r * CIN + k];
    else if (r < 70)  v = w_proj[(r - HCH) * CIN + k];
    g_Bw[r * B_STRIDE + ((k >> 3) << 3) + (k & 3) * 2 + ((k >> 2) & 1)] = to_tf32(v);
    if (k < 8) g_Bw[r * B_STRIDE + 256 + k] = 0u;
}

// ---------------------------------------------------------------------------
// Kernel A (mma.sync tf32): Y[70, NPOS] = [w_dp_f; w_proj] @ p_fea
// CTA = 128 positions, 8 warps = 8 m-tiles of 16. N = 72 (9 n-tiles).
// smem: B copy (19008 w) + 2 x A chunk (k-major, 64 k x 136 stride).
// A frag LDS.32: bank = rr*8 + q (+8) -> conflict-free.
// B frag LDS.64: bank-pair = q*4 + rr -> conflict-free.
// Loader STS (k-major): lanes = consecutive pos -> conflict-free.
// Double-buffered A: LDG chunk c+1 issued before MMA loop on chunk c.
// ---------------------------------------------------------------------------
#define A_STRIDE 136
#define A_WORDS (64 * A_STRIDE)                       // 8704 per buffer
#define GEMM_SMEM ((B_WORDS + 2 * A_WORDS) * 4)       // 145,664 bytes

extern __shared__ uint32_t sm4[];

__global__ void __launch_bounds__(256, 1)
gemm_tc(const float* __restrict__ p_fea) {
    const int tid  = threadIdx.x;
    const int wid  = tid >> 5;
    const int lane = tid & 31;

    // ---- copy pre-packed B verbatim (uint4)
    {
        uint4* dst = (uint4*)sm4;
        const uint4* src = (const uint4*)g_Bw;
#pragma unroll
        for (int i = 0; i < 19; ++i) {
            const int idx = tid + i * 256;
            if (idx < B_WORDS / 4) dst[idx] = src[idx];
        }
    }

    const int tbase = blockIdx.x * 128;
    const int b  = tbase / HWDIM;
    const int s0 = tbase - b * HWDIM;

    // loader role: 128 positions x 2 k-lanes
    const int pos = tid & 127;
    const int kb  = tid >> 7;            // 0 or 1
    const float* gx = p_fea + (size_t)b * (CIN * HWDIM) + s0 + pos;

    // MMA role
    const int mt = wid;                  // m-tile 0..7
    const int q  = lane >> 2;
    const int rr = lane & 3;
    const int arow = mt * 16 + q;

    float d[9][4];
#pragma unroll
    for (int nt = 0; nt < 9; ++nt)
#pragma unroll
        for (int j = 0; j < 4; ++j) d[nt][j] = 0.f;

    uint32_t* Abuf0 = sm4 + B_WORDS;

    // prologue: chunk 0 -> regs -> buf0 (k-major: word = kl*136 + pos)
    float xr[32];
#pragma unroll
    for (int i = 0; i < 32; ++i)
        xr[i] = gx[(size_t)(kb + i * 2) * HWDIM];
#pragma unroll
    for (int i = 0; i < 32; ++i)
        Abuf0[(kb + i * 2) * A_STRIDE + pos] = to_tf32(xr[i]);

#pragma unroll 1
    for (int c = 0; c < 4; ++c) {
        uint32_t* Ac = sm4 + B_WORDS + (c & 1) * A_WORDS;
        uint32_t* An = sm4 + B_WORDS + ((c + 1) & 1) * A_WORDS;

        if (c < 3) {
#pragma unroll
            for (int i = 0; i < 32; ++i)
                xr[i] = gx[(size_t)((c + 1) * 64 + kb + i * 2) * HWDIM];
        }
        __syncthreads();   // buf[c] (and B on c==0) ready

        // MMA over 8 k-steps of this chunk
#pragma unroll
        for (int ks = 0; ks < 8; ++ks) {
            const int kl = ks * 8 + rr;
            const uint32_t a0 = Ac[kl * A_STRIDE + arow];
            const uint32_t a1 = Ac[kl * A_STRIDE + arow + 8];
            const uint32_t a2 = Ac[(kl + 4) * A_STRIDE + arow];
            const uint32_t a3 = Ac[(kl + 4) * A_STRIDE + arow + 8];
            const int bbase = (c * 8 + ks) * 8 + rr * 2;
#pragma unroll
            for (int nt = 0; nt < 9; ++nt) {
                const u64 b01 = *(const u64*)(sm4 + (nt * 8 + q) * B_STRIDE + bbase);
                mma_tf32(d[nt], a0, a1, a2, a3,
                         (uint32_t)b01, (uint32_t)(b01 >> 32));
            }
        }

        if (c < 3) {
#pragma unroll
            for (int i = 0; i < 32; ++i)
                An[(kb + i * 2) * A_STRIDE + pos] = to_tf32(xr[i]);
        }
    }

    // ---- store D to g_Y
    const int pbase = tbase + mt * 16 + q;
#pragma unroll
    for (int nt = 0; nt < 9; ++nt) {
        const int n0 = nt * 8 + rr * 2;
        if (n0 < 70) {
            g_Y[n0 * NPOS + pbase]     = d[nt][0];
            g_Y[n0 * NPOS + pbase + 8] = d[nt][2];
        }
        if (n0 + 1 < 70) {
            g_Y[(n0 + 1) * NPOS + pbase]     = d[nt][1];
            g_Y[(n0 + 1) * NPOS + pbase + 8] = d[nt][3];
        }
    }
}

// ---------------------------------------------------------------------------
// Kernel B: per-position graph epilogue (unchanged).
// ---------------------------------------------------------------------------
__global__ void __launch_bounds__(256, 2)
epi_kernel(const float* __restrict__ xp_stack,
           const float* __restrict__ xh_stack,
           const float* __restrict__ w_att,  const float* __restrict__ b_att,
           const float* __restrict__ w_dp_x, const float* __restrict__ b_dp,
           const float* __restrict__ b_proj,
           const float* __restrict__ w_gate, const float* __restrict__ b_gate,
           const float* __restrict__ w_upd,  const float* __restrict__ b_upd,
           float* __restrict__ out) {
    __shared__ float cw[2222];
    for (int i = threadIdx.x; i < 2222; i += 256) {
        float v;
        if      (i < 60)   v = w_att[i];
        else if (i < 66)   v = b_att[i - 60];
        else if (i < 166)  v = w_dp_x[i - 66];
        else if (i < 176)  v = b_dp[i - 166];
        else if (i < 236)  v = b_proj[i - 176];
        else if (i < 356)  v = w_gate[i - 236];
        else if (i < 362)  v = b_gate[i - 356];
        else if (i < 2162) v = w_upd[i - 362];
        else               v = b_upd[i - 2162];
        cw[i] = v;
    }
    __syncthreads();

    const float* sW_att  = cw;
    const float* sB_att  = cw + 60;
    const float* sW_dpx  = cw + 66;
    const float* sB_dp   = cw + 166;
    const float* sB_proj = cw + 176;
    const float* sW_gate = cw + 236;
    const float* sB_gate = cw + 356;
    const float* sW_upd  = cw + 362;
    const float* sB_upd  = cw + 2162;

    const int n = blockIdx.x * 256 + threadIdx.x;
    const int b = n / HWDIM;
    const int s = n - b * HWDIM;
    const int bbase = b * (HCH * HWDIM) + s;

    float fdp[HCH];
#pragma unroll
    for (int d = 0; d < HCH; ++d)
        fdp[d] = g_Y[d * NPOS + n] + sB_dp[d];

    float att[NPARTS];
    float dp1[HCH], S[HCH], xp1[HCH];
    float attsum = 0.f;
#pragma unroll
    for (int d = 0; d < HCH; ++d) S[d] = 0.f;

#pragma unroll
    for (int p = 0; p < NPARTS; ++p) {
        const float* xpp_ptr = xp_stack + p * PBH + bbase;
        float xq[HCH];
#pragma unroll
        for (int d = 0; d < HCH; ++d) xq[d] = xpp_ptr[d * HWDIM];

        float a = sB_att[p];
#pragma unroll
        for (int d = 0; d < HCH; ++d) a += sW_att[p * HCH + d] * xq[d];
        a = sigm(a);
        att[p] = a;

        float dpv[HCH];
#pragma unroll
        for (int d = 0; d < HCH; ++d) {
            float u = fdp[d];
#pragma unroll
            for (int e = 0; e < HCH; ++e) u += sW_dpx[d * HCH + e] * xq[e];
            dpv[d] = fmaxf(u, 0.f);
        }
        if (p == 1) {
#pragma unroll
            for (int d = 0; d < HCH; ++d) { dp1[d] = dpv[d]; xp1[d] = xq[d]; }
        } else {
            attsum += a;
#pragma unroll
            for (int d = 0; d < HCH; ++d) S[d] += a * dpv[d];
        }
    }

#pragma unroll
    for (int p = 0; p < NPARTS; ++p) {
        const float* xpp_ptr = xp_stack + p * PBH + bbase;
        float xq[HCH];
        if (p == 1) {
#pragma unroll
            for (int d = 0; d < HCH; ++d) xq[d] = xp1[d];
        } else {
#pragma unroll
            for (int d = 0; d < HCH; ++d) xq[d] = xpp_ptr[d * HWDIM];
        }

        float xppv[HCH];
        if (p == 1) {
#pragma unroll
            for (int d = 0; d < HCH; ++d)
                xppv[d] = att[1] * (S[d] + attsum * xp1[d]);
        } else {
            const float aa = att[1] * att[p];
#pragma unroll
            for (int d = 0; d < HCH; ++d)
                xppv[d] = aa * (dp1[d] + xq[d]);
        }

        const int hf = (p < 4) ? 0 : 1;
        const float* xh_ptr = xh_stack + hf * PBH + bbase;
        float gsum = sB_gate[p];
#pragma unroll
        for (int d = 0; d < HCH; ++d)
            gsum += sW_gate[p * 2 * HCH + d] * xh_ptr[d * HWDIM];
#pragma unroll
        for (int d = 0; d < HCH; ++d)
            gsum += sW_gate[p * 2 * HCH + HCH + d] * xq[d];
        const float gate = sigm(gsum);

        float xhpv[HCH];
#pragma unroll
        for (int d = 0; d < HCH; ++d)
            xhpv[d] = gate * (g_Y[(HCH + p * HCH + d) * NPOS + n] + sB_proj[p * HCH + d]);

        float* o0 = out + p * PBH + bbase;
#pragma unroll
        for (int d = 0; d < HCH; ++d) {
            float u = sB_upd[p * HCH + d];
            const float* wr = sW_upd + (p * HCH + d) * (3 * HCH);
#pragma unroll
            for (int e = 0; e < HCH; ++e) u += wr[e] * xq[e];
#pragma unroll
            for (int e = 0; e < HCH; ++e) u += wr[HCH + e] * xppv[e];
#pragma unroll
            for (int e = 0; e < HCH; ++e) u += wr[2 * HCH + e] * xhpv[e];
            const float o = xq[d] + fmaxf(u, 0.f);

            const int doff = d * HWDIM;
            o0[doff]                = o;
            o0[PART_SZ + doff]      = xppv[d];
            o0[2 * PART_SZ + doff]  = xhpv[d];
        }
    }
}

// ---------------------------------------------------------------------------
extern "C" void kernel_launch(void* const* d_in, const int* in_sizes, int n_in,
                              void* d_out, int out_size) {
    const float* p_fea  = (const float*)d_in[0];
    const float* xp     = (const float*)d_in[1];
    const float* xh     = (const float*)d_in[2];
    const float* w_att  = (const float*)d_in[3];
    const float* b_att  = (const float*)d_in[4];
    const float* w_dp_f = (const float*)d_in[5];
    const float* w_dp_x = (const float*)d_in[6];
    const float* b_dp   = (const float*)d_in[7];
    const float* w_proj = (const float*)d_in[8];
    const float* b_proj = (const float*)d_in[9];
    const float* w_gate = (const float*)d_in[10];
    const float* b_gate = (const float*)d_in[11];
    const float* w_upd  = (const float*)d_in[12];
    const float* b_upd  = (const float*)d_in[13];
    float* out = (float*)d_out;

    cudaFuncSetAttribute(gemm_tc, cudaFuncAttributeMaxDynamicSharedMemorySize,
                         GEMM_SMEM);

    prep_kernel<<<72, 256>>>(w_dp_f, w_proj);
    gemm_tc<<<NPOS / 128, 256, GEMM_SMEM>>>(p_fea);
    epi_kernel<<<NPOS / 256, 256>>>(xp, xh, w_att, b_att, w_dp_x, b_dp,
                                    b_proj, w_gate, b_gate, w_upd, b_upd, out);
}